// round 1
// baseline (speedup 1.0000x reference)
#include <cuda_runtime.h>
#include <math.h>

// Problem constants
#define NB    2
#define NT    2048
#define ND    768
#define NH    12
#define NHS   64
#define NFF   3072
#define NHALF 1536
#define NBT   (NB*NT)   // 4096

// ---------------- scratch (device globals; no allocation) ----------------
__device__ float g_h   [NBT * ND];        // rmsnorm output (reused for h2)
__device__ float g_qkv [NBT * 3 * ND];    // fused qkv: cols [0,768)=Q [768,1536)=K [1536,2304)=V
__device__ float g_attn[NBT * ND];        // attention output (heads concatenated)
__device__ float g_x1  [NBT * ND];        // residual after attention
__device__ float g_u   [NBT * NFF];       // FFN1 output
__device__ float g_gl  [NBT * NHALF];     // silu(gate)*a
__device__ float g_wqkv[ND * 3 * ND];     // packed QKV weight [768 x 2304]

// ---------------- pack Wq/Wk/Wv (H,D,HS) -> B[768][2304] ----------------
__global__ void pack_wqkv_kernel(const float* __restrict__ Wq,
                                 const float* __restrict__ Wk,
                                 const float* __restrict__ Wv)
{
    int idx = blockIdx.x * blockDim.x + threadIdx.x;
    const int total = ND * 3 * ND;
    if (idx >= total) return;
    int d = idx / (3 * ND);
    int n = idx % (3 * ND);
    int m = n / ND;            // 0=Q 1=K 2=V
    int r = n % ND;
    int h = r / NHS;
    int k = r % NHS;
    const float* W = (m == 0) ? Wq : ((m == 1) ? Wk : Wv);
    g_wqkv[idx] = W[h * ND * NHS + d * NHS + k];
}

// ---------------- RMSNorm (row = 768, block = 256 threads) ----------------
__device__ __forceinline__ void rms_body(const float* __restrict__ in,
                                         float* __restrict__ out,
                                         const float* __restrict__ g)
{
    int tid = threadIdx.x;
    float v0 = in[tid], v1 = in[tid + 256], v2 = in[tid + 512];
    float ss = v0*v0 + v1*v1 + v2*v2;
    #pragma unroll
    for (int o = 16; o; o >>= 1) ss += __shfl_xor_sync(0xffffffffu, ss, o);
    __shared__ float ws[8];
    __shared__ float s_inv;
    if ((tid & 31) == 0) ws[tid >> 5] = ss;
    __syncthreads();
    if (tid == 0) {
        float t = 0.f;
        #pragma unroll
        for (int i = 0; i < 8; i++) t += ws[i];
        float rms = sqrtf(t * (1.0f / (float)ND));
        s_inv = 1.0f / (rms + 1e-8f);
    }
    __syncthreads();
    float inv = s_inv;
    out[tid]       = g[tid]       * v0 * inv;
    out[tid + 256] = g[tid + 256] * v1 * inv;
    out[tid + 512] = g[tid + 512] * v2 * inv;
}

__global__ __launch_bounds__(256) void rmsnorm1_kernel(const float* __restrict__ x,
                                                       const float* __restrict__ g)
{
    int row = blockIdx.x;
    rms_body(x + (size_t)row * ND, g_h + (size_t)row * ND, g);
}

__global__ __launch_bounds__(256) void rmsnorm2_kernel(const float* __restrict__ g)
{
    int row = blockIdx.x;
    rms_body(g_x1 + (size_t)row * ND, g_h + (size_t)row * ND, g);
}

// ---------------- SGEMM: 128x128x16 tile, 8x8 microtile, 256 threads ------
// C[M,N] = A[M,K] @ B[K,N] (+bias[N]) (+res[M,N]); M = 4096 always.
template<int N, int K, bool BIAS, bool RES>
__device__ __forceinline__ void gemm_body(const float* __restrict__ A,
                                          const float* __restrict__ Bm,
                                          float* __restrict__ C,
                                          const float* __restrict__ bias,
                                          const float* __restrict__ res)
{
    __shared__ float As[16][132];   // transposed A tile, padded
    __shared__ float Bs[16][128];

    const int tid = threadIdx.x;
    const int bm = blockIdx.y * 128;
    const int bn = blockIdx.x * 128;
    const int tx = tid & 15;        // column group
    const int ty = tid >> 4;        // row group
    const int a_row = tid >> 2;             // 0..63
    const int a_col = (tid & 3) << 2;       // 0,4,8,12
    const int b_row = tid >> 5;             // 0..7
    const int b_col = (tid & 31) << 2;      // 0..124

    float acc[8][8];
    #pragma unroll
    for (int i = 0; i < 8; i++)
        #pragma unroll
        for (int j = 0; j < 8; j++) acc[i][j] = 0.f;

    #pragma unroll 1
    for (int k0 = 0; k0 < K; k0 += 16) {
        #pragma unroll
        for (int r = 0; r < 2; r++) {
            int row = a_row + 64 * r;
            float4 v = *(const float4*)(A + (size_t)(bm + row) * K + k0 + a_col);
            As[a_col + 0][row] = v.x;
            As[a_col + 1][row] = v.y;
            As[a_col + 2][row] = v.z;
            As[a_col + 3][row] = v.w;
        }
        #pragma unroll
        for (int r = 0; r < 2; r++) {
            int row = b_row + 8 * r;
            *(float4*)&Bs[row][b_col] =
                *(const float4*)(Bm + (size_t)(k0 + row) * N + bn + b_col);
        }
        __syncthreads();
        #pragma unroll
        for (int kk = 0; kk < 16; kk++) {
            float af[8], bf[8];
            #pragma unroll
            for (int i = 0; i < 8; i++) af[i] = As[kk][ty * 8 + i];
            #pragma unroll
            for (int j = 0; j < 8; j++) bf[j] = Bs[kk][tx * 8 + j];
            #pragma unroll
            for (int i = 0; i < 8; i++)
                #pragma unroll
                for (int j = 0; j < 8; j++)
                    acc[i][j] = fmaf(af[i], bf[j], acc[i][j]);
        }
        __syncthreads();
    }

    #pragma unroll
    for (int i = 0; i < 8; i++) {
        int row = bm + ty * 8 + i;
        #pragma unroll
        for (int j4 = 0; j4 < 2; j4++) {
            int col = bn + tx * 8 + j4 * 4;
            float4 c;
            c.x = acc[i][j4*4+0]; c.y = acc[i][j4*4+1];
            c.z = acc[i][j4*4+2]; c.w = acc[i][j4*4+3];
            if constexpr (BIAS) {
                float4 bb = *(const float4*)(bias + col);
                c.x += bb.x; c.y += bb.y; c.z += bb.z; c.w += bb.w;
            }
            if constexpr (RES) {
                float4 rr = *(const float4*)(res + (size_t)row * N + col);
                c.x += rr.x; c.y += rr.y; c.z += rr.z; c.w += rr.w;
            }
            *(float4*)(C + (size_t)row * N + col) = c;
        }
    }
}

__global__ __launch_bounds__(256) void gemm_qkv_kernel()
{
    gemm_body<3 * ND, ND, false, false>(g_h, g_wqkv, g_qkv, nullptr, nullptr);
}
__global__ __launch_bounds__(256) void gemm_o_kernel(const float* __restrict__ Wo,
                                                     const float* __restrict__ bo,
                                                     const float* __restrict__ x)
{
    gemm_body<ND, ND, true, true>(g_attn, Wo, g_x1, bo, x);
}
__global__ __launch_bounds__(256) void gemm_ffn1_kernel(const float* __restrict__ W1,
                                                        const float* __restrict__ b1)
{
    gemm_body<NFF, ND, true, false>(g_h, W1, g_u, b1, nullptr);
}
__global__ __launch_bounds__(256) void gemm_ffn2_kernel(const float* __restrict__ W2,
                                                        const float* __restrict__ b2,
                                                        float* __restrict__ out)
{
    gemm_body<ND, NHALF, true, true>(g_gl, W2, out, b2, g_x1);
}

// ---------------- Flash attention: 64x64 tiles, online softmax -------------
// grid (T/64, H, B), 256 threads, dynamic smem.
__global__ __launch_bounds__(256) void attn_kernel()
{
    extern __shared__ float sm[];
    float* Qs  = sm;                 // [64][65]
    float* Ks  = Qs + 64 * 65;       // [64][65]
    float* Vs  = Ks + 64 * 65;       // [64][65]
    float* Ps  = Vs + 64 * 65;       // [64][65]
    float* m_s = Ps + 64 * 65;       // [64]
    float* l_s = m_s + 64;           // [64]
    float* al_s = l_s + 64;          // [64]

    const int tid = threadIdx.x;
    const int qb = blockIdx.x;
    const int h  = blockIdx.y;
    const int b  = blockIdx.z;
    const int tx = tid & 15;         // 4-col group of S/O
    const int ty = tid >> 4;         // 4-row group
    const int warp = tid >> 5, lane = tid & 31;

    const int lr = tid >> 4;         // loader row 0..15
    const int lc = (tid & 15) * 4;   // loader col group

    // Load Q tile (rows qb*64..qb*64+63, head h)
    #pragma unroll
    for (int r = 0; r < 4; r++) {
        int row = lr + 16 * r;
        float4 v = *(const float4*)&g_qkv[(size_t)(b * NT + qb * 64 + row) * (3 * ND)
                                          + h * NHS + lc];
        Qs[row * 65 + lc + 0] = v.x;
        Qs[row * 65 + lc + 1] = v.y;
        Qs[row * 65 + lc + 2] = v.z;
        Qs[row * 65 + lc + 3] = v.w;
    }
    if (tid < 64) { m_s[tid] = -1e30f; l_s[tid] = 0.f; }

    float o[4][4];
    #pragma unroll
    for (int i = 0; i < 4; i++)
        #pragma unroll
        for (int j = 0; j < 4; j++) o[i][j] = 0.f;

    const float scale = 0.03608439182435161f;   // 768^-0.5
    __syncthreads();

    for (int jb = 0; jb <= qb; jb++) {
        // Load K, V tiles
        #pragma unroll
        for (int r = 0; r < 4; r++) {
            int row = lr + 16 * r;
            size_t base = (size_t)(b * NT + jb * 64 + row) * (3 * ND) + h * NHS + lc;
            float4 kv = *(const float4*)&g_qkv[ND + base];
            float4 vv = *(const float4*)&g_qkv[2 * ND + base];
            Ks[row * 65 + lc + 0] = kv.x; Ks[row * 65 + lc + 1] = kv.y;
            Ks[row * 65 + lc + 2] = kv.z; Ks[row * 65 + lc + 3] = kv.w;
            Vs[row * 65 + lc + 0] = vv.x; Vs[row * 65 + lc + 1] = vv.y;
            Vs[row * 65 + lc + 2] = vv.z; Vs[row * 65 + lc + 3] = vv.w;
        }
        __syncthreads();

        // S = Q @ K^T  (4x4 per thread)
        float s[4][4];
        #pragma unroll
        for (int i = 0; i < 4; i++)
            #pragma unroll
            for (int j = 0; j < 4; j++) s[i][j] = 0.f;
        #pragma unroll 8
        for (int k = 0; k < 64; k++) {
            float qa[4], kb[4];
            #pragma unroll
            for (int i = 0; i < 4; i++) qa[i] = Qs[(ty * 4 + i) * 65 + k];
            #pragma unroll
            for (int j = 0; j < 4; j++) kb[j] = Ks[(tx * 4 + j) * 65 + k];
            #pragma unroll
            for (int i = 0; i < 4; i++)
                #pragma unroll
                for (int j = 0; j < 4; j++)
                    s[i][j] = fmaf(qa[i], kb[j], s[i][j]);
        }

        const bool diag = (jb == qb);
        #pragma unroll
        for (int i = 0; i < 4; i++) {
            int qpos = qb * 64 + ty * 4 + i;
            #pragma unroll
            for (int j = 0; j < 4; j++) {
                int kpos = jb * 64 + tx * 4 + j;
                float v = s[i][j] * scale;
                if (diag && kpos > qpos) v = -1e30f;
                Ps[(ty * 4 + i) * 65 + tx * 4 + j] = v;
            }
        }
        __syncthreads();

        // Online softmax: warp w owns rows [w*8, w*8+8)
        #pragma unroll
        for (int rr = 0; rr < 8; rr++) {
            int row = warp * 8 + rr;
            float v0 = Ps[row * 65 + lane * 2];
            float v1 = Ps[row * 65 + lane * 2 + 1];
            float mx = fmaxf(v0, v1);
            #pragma unroll
            for (int off = 16; off; off >>= 1)
                mx = fmaxf(mx, __shfl_xor_sync(0xffffffffu, mx, off));
            float mold = m_s[row];
            float mnew = fmaxf(mold, mx);
            float p0 = __expf(v0 - mnew);
            float p1 = __expf(v1 - mnew);
            float ps = p0 + p1;
            #pragma unroll
            for (int off = 16; off; off >>= 1)
                ps += __shfl_xor_sync(0xffffffffu, ps, off);
            if (lane == 0) {
                float al = __expf(mold - mnew);
                al_s[row] = al;
                l_s[row] = l_s[row] * al + ps;
                m_s[row] = mnew;
            }
            Ps[row * 65 + lane * 2]     = p0;
            Ps[row * 65 + lane * 2 + 1] = p1;
        }
        __syncthreads();

        // Rescale O, then O += P @ V
        float al[4];
        #pragma unroll
        for (int i = 0; i < 4; i++) al[i] = al_s[ty * 4 + i];
        #pragma unroll
        for (int i = 0; i < 4; i++)
            #pragma unroll
            for (int j = 0; j < 4; j++) o[i][j] *= al[i];

        #pragma unroll 8
        for (int j = 0; j < 64; j++) {
            float pa[4], vb[4];
            #pragma unroll
            for (int i = 0; i < 4; i++) pa[i] = Ps[(ty * 4 + i) * 65 + j];
            #pragma unroll
            for (int c = 0; c < 4; c++) vb[c] = Vs[j * 65 + tx * 4 + c];
            #pragma unroll
            for (int i = 0; i < 4; i++)
                #pragma unroll
                for (int c = 0; c < 4; c++)
                    o[i][c] = fmaf(pa[i], vb[c], o[i][c]);
        }
        __syncthreads();
    }

    // Normalize and write out (concat heads layout)
    float linv[4];
    #pragma unroll
    for (int i = 0; i < 4; i++) linv[i] = 1.0f / l_s[ty * 4 + i];
    #pragma unroll
    for (int i = 0; i < 4; i++) {
        int row = b * NT + qb * 64 + ty * 4 + i;
        #pragma unroll
        for (int c = 0; c < 4; c++)
            g_attn[(size_t)row * ND + h * NHS + tx * 4 + c] = o[i][c] * linv[i];
    }
}

// ---------------- SwiGLU elementwise ----------------
__global__ void swiglu_kernel()
{
    int idx = blockIdx.x * blockDim.x + threadIdx.x;
    if (idx >= NBT * NHALF) return;
    int row = idx / NHALF;
    int c   = idx % NHALF;
    float a = g_u[(size_t)row * NFF + c];
    float z = g_u[(size_t)row * NFF + NHALF + c];
    float sg = z / (1.0f + __expf(-z));
    g_gl[idx] = sg * a;
}

// ---------------- launch ----------------
extern "C" void kernel_launch(void* const* d_in, const int* in_sizes, int n_in,
                              void* d_out, int out_size)
{
    const float* x  = (const float*)d_in[0];
    const float* Wq = (const float*)d_in[1];
    const float* Wk = (const float*)d_in[2];
    const float* Wv = (const float*)d_in[3];
    const float* Wo = (const float*)d_in[4];
    const float* bo = (const float*)d_in[5];
    const float* W1 = (const float*)d_in[6];
    const float* b1 = (const float*)d_in[7];
    const float* W2 = (const float*)d_in[8];
    const float* b2 = (const float*)d_in[9];
    const float* g1 = (const float*)d_in[10];
    const float* g2 = (const float*)d_in[11];
    float* out = (float*)d_out;

    const int ASMEM = (4 * 64 * 65 + 3 * 64) * (int)sizeof(float);  // 67328 B
    cudaFuncSetAttribute(attn_kernel, cudaFuncAttributeMaxDynamicSharedMemorySize, ASMEM);

    // 1. pack fused QKV weight
    pack_wqkv_kernel<<<(ND * 3 * ND + 255) / 256, 256>>>(Wq, Wk, Wv);
    // 2. rmsnorm1
    rmsnorm1_kernel<<<NBT, 256>>>(x, g1);
    // 3. fused QKV GEMM  [4096 x 2304]
    gemm_qkv_kernel<<<dim3(3 * ND / 128, NBT / 128), 256>>>();
    // 4. causal flash attention
    attn_kernel<<<dim3(NT / 64, NH, NB), 256, ASMEM>>>();
    // 5. Wo projection + bias + residual -> x1
    gemm_o_kernel<<<dim3(ND / 128, NBT / 128), 256>>>(Wo, bo, x);
    // 6. rmsnorm2
    rmsnorm2_kernel<<<NBT, 256>>>(g2);
    // 7. FFN1
    gemm_ffn1_kernel<<<dim3(NFF / 128, NBT / 128), 256>>>(W1, b1);
    // 8. SwiGLU
    swiglu_kernel<<<(NBT * NHALF + 255) / 256, 256>>>();
    // 9. FFN2 + bias + residual -> out
    gemm_ffn2_kernel<<<dim3(ND / 128, NBT / 128), 256>>>(W2, b2, out);
}

// round 2
// speedup vs baseline: 1.7643x; 1.7643x over previous
#include <cuda_runtime.h>
#include <math.h>
#include <stdint.h>

// Problem constants
#define NB    2
#define NT    2048
#define ND    768
#define NH    12
#define NHS   64
#define NFF   3072
#define NHALF 1536
#define NBT   (NB*NT)   // 4096

// ---------------- scratch (device globals; no allocation) ----------------
__device__ float g_h   [NBT * ND];        // rmsnorm output (reused for h2)
__device__ float g_qkv [NBT * 3 * ND];    // fused qkv
__device__ float g_attn[NBT * ND];        // attention output
__device__ float g_x1  [NBT * ND];        // residual after attention
__device__ float g_u   [NBT * NFF];       // FFN1 output
__device__ float g_gl  [NBT * NHALF];     // silu(gate)*a
__device__ float g_wqkv[ND * 3 * ND];     // packed QKV weight [768 x 2304]

// ---------------- pack Wq/Wk/Wv (H,D,HS) -> B[768][2304] ----------------
__global__ void pack_wqkv_kernel(const float* __restrict__ Wq,
                                 const float* __restrict__ Wk,
                                 const float* __restrict__ Wv)
{
    int idx = blockIdx.x * blockDim.x + threadIdx.x;
    const int total = ND * 3 * ND;
    if (idx >= total) return;
    int d = idx / (3 * ND);
    int n = idx % (3 * ND);
    int m = n / ND;
    int r = n % ND;
    int h = r / NHS;
    int k = r % NHS;
    const float* W = (m == 0) ? Wq : ((m == 1) ? Wk : Wv);
    g_wqkv[idx] = W[h * ND * NHS + d * NHS + k];
}

// ---------------- RMSNorm ----------------
__device__ __forceinline__ void rms_body(const float* __restrict__ in,
                                         float* __restrict__ out,
                                         const float* __restrict__ g)
{
    int tid = threadIdx.x;
    float v0 = in[tid], v1 = in[tid + 256], v2 = in[tid + 512];
    float ss = v0*v0 + v1*v1 + v2*v2;
    #pragma unroll
    for (int o = 16; o; o >>= 1) ss += __shfl_xor_sync(0xffffffffu, ss, o);
    __shared__ float ws[8];
    __shared__ float s_inv;
    if ((tid & 31) == 0) ws[tid >> 5] = ss;
    __syncthreads();
    if (tid == 0) {
        float t = 0.f;
        #pragma unroll
        for (int i = 0; i < 8; i++) t += ws[i];
        float rms = sqrtf(t * (1.0f / (float)ND));
        s_inv = 1.0f / (rms + 1e-8f);
    }
    __syncthreads();
    float inv = s_inv;
    out[tid]       = g[tid]       * v0 * inv;
    out[tid + 256] = g[tid + 256] * v1 * inv;
    out[tid + 512] = g[tid + 512] * v2 * inv;
}

__global__ __launch_bounds__(256) void rmsnorm1_kernel(const float* __restrict__ x,
                                                       const float* __restrict__ g)
{
    int row = blockIdx.x;
    rms_body(x + (size_t)row * ND, g_h + (size_t)row * ND, g);
}

__global__ __launch_bounds__(256) void rmsnorm2_kernel(const float* __restrict__ g)
{
    int row = blockIdx.x;
    rms_body(g_x1 + (size_t)row * ND, g_h + (size_t)row * ND, g);
}

// ---------------- TF32 tensor-core GEMM ----------------
// 128x128 tile, Kc=32, 8 warps, each warp = 32x64 (2x8 m16n8k8 MMAs).

__device__ __forceinline__ float tf32r(float x)
{
    uint32_t r;
    asm("cvt.rna.tf32.f32 %0, %1;" : "=r"(r) : "f"(x));
    return __uint_as_float(r);
}

__device__ __forceinline__ void mma_tf32(float* c, const uint32_t* a, const uint32_t* b)
{
    asm volatile(
        "mma.sync.aligned.m16n8k8.row.col.f32.tf32.tf32.f32 "
        "{%0,%1,%2,%3}, {%4,%5,%6,%7}, {%8,%9}, {%0,%1,%2,%3};\n"
        : "+f"(c[0]), "+f"(c[1]), "+f"(c[2]), "+f"(c[3])
        : "r"(a[0]), "r"(a[1]), "r"(a[2]), "r"(a[3]), "r"(b[0]), "r"(b[1]));
}

template<int N, int K, bool BIAS, bool RES>
__device__ __forceinline__ void mma_gemm_body(const float* __restrict__ A,
                                              const float* __restrict__ Bm,
                                              float* __restrict__ C,
                                              const float* __restrict__ bias,
                                              const float* __restrict__ res)
{
    __shared__ float As[128][36];    // A tile [row][k], stride 36 -> conflict-free frag loads
    __shared__ float Bs[32][136];    // B tile [k][col], stride 136

    const int tid  = threadIdx.x;
    const int warp = tid >> 5, lane = tid & 31;
    const int wm = (warp >> 1) * 32;  // warp row offset in tile
    const int wn = (warp & 1) * 64;   // warp col offset in tile
    const int bm = blockIdx.y * 128;
    const int bn = blockIdx.x * 128;

    const int lrow = tid >> 3;        // 0..31
    const int lcol = (tid & 7) * 4;   // 0,4,...,28

    float acc[2][8][4];
    #pragma unroll
    for (int i = 0; i < 2; i++)
        #pragma unroll
        for (int j = 0; j < 8; j++)
            #pragma unroll
            for (int t = 0; t < 4; t++) acc[i][j][t] = 0.f;

    #pragma unroll 1
    for (int k0 = 0; k0 < K; k0 += 32) {
        // A: 128 rows x 32 k
        #pragma unroll
        for (int r = 0; r < 4; r++) {
            int row = lrow + 32 * r;
            float4 v = *(const float4*)(A + (size_t)(bm + row) * K + k0 + lcol);
            As[row][lcol + 0] = tf32r(v.x);
            As[row][lcol + 1] = tf32r(v.y);
            As[row][lcol + 2] = tf32r(v.z);
            As[row][lcol + 3] = tf32r(v.w);
        }
        // B: 32 k x 128 cols
        #pragma unroll
        for (int c = 0; c < 4; c++) {
            int col = lcol + 32 * c;
            float4 v = *(const float4*)(Bm + (size_t)(k0 + lrow) * N + bn + col);
            Bs[lrow][col + 0] = tf32r(v.x);
            Bs[lrow][col + 1] = tf32r(v.y);
            Bs[lrow][col + 2] = tf32r(v.z);
            Bs[lrow][col + 3] = tf32r(v.w);
        }
        __syncthreads();

        #pragma unroll
        for (int kk = 0; kk < 32; kk += 8) {
            uint32_t aF[2][4], bF[8][2];
            #pragma unroll
            for (int mt = 0; mt < 2; mt++) {
                int r = wm + mt * 16 + (lane >> 2);
                int c = kk + (lane & 3);
                aF[mt][0] = __float_as_uint(As[r][c]);
                aF[mt][1] = __float_as_uint(As[r + 8][c]);
                aF[mt][2] = __float_as_uint(As[r][c + 4]);
                aF[mt][3] = __float_as_uint(As[r + 8][c + 4]);
            }
            #pragma unroll
            for (int nt = 0; nt < 8; nt++) {
                int rr = kk + (lane & 3);
                int cc = wn + nt * 8 + (lane >> 2);
                bF[nt][0] = __float_as_uint(Bs[rr][cc]);
                bF[nt][1] = __float_as_uint(Bs[rr + 4][cc]);
            }
            #pragma unroll
            for (int mt = 0; mt < 2; mt++)
                #pragma unroll
                for (int nt = 0; nt < 8; nt++)
                    mma_tf32(acc[mt][nt], aF[mt], bF[nt]);
        }
        __syncthreads();
    }

    // Epilogue: c0,c1 at (row, col+0/1); c2,c3 at (row+8, col+0/1)
    #pragma unroll
    for (int mt = 0; mt < 2; mt++) {
        #pragma unroll
        for (int nt = 0; nt < 8; nt++) {
            int row0 = bm + wm + mt * 16 + (lane >> 2);
            int col  = bn + wn + nt * 8 + (lane & 3) * 2;
            float2 v0 = make_float2(acc[mt][nt][0], acc[mt][nt][1]);
            float2 v1 = make_float2(acc[mt][nt][2], acc[mt][nt][3]);
            if constexpr (BIAS) {
                float2 bb = *(const float2*)(bias + col);
                v0.x += bb.x; v0.y += bb.y;
                v1.x += bb.x; v1.y += bb.y;
            }
            if constexpr (RES) {
                float2 r0 = *(const float2*)(res + (size_t)row0 * N + col);
                float2 r1 = *(const float2*)(res + (size_t)(row0 + 8) * N + col);
                v0.x += r0.x; v0.y += r0.y;
                v1.x += r1.x; v1.y += r1.y;
            }
            *(float2*)(C + (size_t)row0 * N + col)       = v0;
            *(float2*)(C + (size_t)(row0 + 8) * N + col) = v1;
        }
    }
}

__global__ __launch_bounds__(256) void gemm_qkv_kernel()
{
    mma_gemm_body<3 * ND, ND, false, false>(g_h, g_wqkv, g_qkv, nullptr, nullptr);
}
__global__ __launch_bounds__(256) void gemm_o_kernel(const float* __restrict__ Wo,
                                                     const float* __restrict__ bo,
                                                     const float* __restrict__ x)
{
    mma_gemm_body<ND, ND, true, true>(g_attn, Wo, g_x1, bo, x);
}
__global__ __launch_bounds__(256) void gemm_ffn1_kernel(const float* __restrict__ W1,
                                                        const float* __restrict__ b1)
{
    mma_gemm_body<NFF, ND, true, false>(g_h, W1, g_u, b1, nullptr);
}
__global__ __launch_bounds__(256) void gemm_ffn2_kernel(const float* __restrict__ W2,
                                                        const float* __restrict__ b2,
                                                        float* __restrict__ out)
{
    mma_gemm_body<ND, NHALF, true, true>(g_gl, W2, out, b2, g_x1);
}

// ---------------- Flash attention: 64x64 tiles, online softmax -------------
__global__ __launch_bounds__(256) void attn_kernel()
{
    extern __shared__ float sm[];
    float* Qs  = sm;                 // [64][65]
    float* Ks  = Qs + 64 * 65;
    float* Vs  = Ks + 64 * 65;
    float* Ps  = Vs + 64 * 65;
    float* m_s = Ps + 64 * 65;
    float* l_s = m_s + 64;
    float* al_s = l_s + 64;

    const int tid = threadIdx.x;
    const int qb = blockIdx.x;
    const int h  = blockIdx.y;
    const int b  = blockIdx.z;
    const int tx = tid & 15;
    const int ty = tid >> 4;
    const int warp = tid >> 5, lane = tid & 31;

    const int lr = tid >> 4;
    const int lc = (tid & 15) * 4;

    #pragma unroll
    for (int r = 0; r < 4; r++) {
        int row = lr + 16 * r;
        float4 v = *(const float4*)&g_qkv[(size_t)(b * NT + qb * 64 + row) * (3 * ND)
                                          + h * NHS + lc];
        Qs[row * 65 + lc + 0] = v.x;
        Qs[row * 65 + lc + 1] = v.y;
        Qs[row * 65 + lc + 2] = v.z;
        Qs[row * 65 + lc + 3] = v.w;
    }
    if (tid < 64) { m_s[tid] = -1e30f; l_s[tid] = 0.f; }

    float o[4][4];
    #pragma unroll
    for (int i = 0; i < 4; i++)
        #pragma unroll
        for (int j = 0; j < 4; j++) o[i][j] = 0.f;

    const float scale = 0.03608439182435161f;   // 768^-0.5
    __syncthreads();

    for (int jb = 0; jb <= qb; jb++) {
        #pragma unroll
        for (int r = 0; r < 4; r++) {
            int row = lr + 16 * r;
            size_t base = (size_t)(b * NT + jb * 64 + row) * (3 * ND) + h * NHS + lc;
            float4 kv = *(const float4*)&g_qkv[ND + base];
            float4 vv = *(const float4*)&g_qkv[2 * ND + base];
            Ks[row * 65 + lc + 0] = kv.x; Ks[row * 65 + lc + 1] = kv.y;
            Ks[row * 65 + lc + 2] = kv.z; Ks[row * 65 + lc + 3] = kv.w;
            Vs[row * 65 + lc + 0] = vv.x; Vs[row * 65 + lc + 1] = vv.y;
            Vs[row * 65 + lc + 2] = vv.z; Vs[row * 65 + lc + 3] = vv.w;
        }
        __syncthreads();

        float s[4][4];
        #pragma unroll
        for (int i = 0; i < 4; i++)
            #pragma unroll
            for (int j = 0; j < 4; j++) s[i][j] = 0.f;
        #pragma unroll 8
        for (int k = 0; k < 64; k++) {
            float qa[4], kb[4];
            #pragma unroll
            for (int i = 0; i < 4; i++) qa[i] = Qs[(ty * 4 + i) * 65 + k];
            #pragma unroll
            for (int j = 0; j < 4; j++) kb[j] = Ks[(tx * 4 + j) * 65 + k];
            #pragma unroll
            for (int i = 0; i < 4; i++)
                #pragma unroll
                for (int j = 0; j < 4; j++)
                    s[i][j] = fmaf(qa[i], kb[j], s[i][j]);
        }

        const bool diag = (jb == qb);
        #pragma unroll
        for (int i = 0; i < 4; i++) {
            int qpos = qb * 64 + ty * 4 + i;
            #pragma unroll
            for (int j = 0; j < 4; j++) {
                int kpos = jb * 64 + tx * 4 + j;
                float v = s[i][j] * scale;
                if (diag && kpos > qpos) v = -1e30f;
                Ps[(ty * 4 + i) * 65 + tx * 4 + j] = v;
            }
        }
        __syncthreads();

        #pragma unroll
        for (int rr = 0; rr < 8; rr++) {
            int row = warp * 8 + rr;
            float v0 = Ps[row * 65 + lane * 2];
            float v1 = Ps[row * 65 + lane * 2 + 1];
            float mx = fmaxf(v0, v1);
            #pragma unroll
            for (int off = 16; off; off >>= 1)
                mx = fmaxf(mx, __shfl_xor_sync(0xffffffffu, mx, off));
            float mold = m_s[row];
            float mnew = fmaxf(mold, mx);
            float p0 = __expf(v0 - mnew);
            float p1 = __expf(v1 - mnew);
            float ps = p0 + p1;
            #pragma unroll
            for (int off = 16; off; off >>= 1)
                ps += __shfl_xor_sync(0xffffffffu, ps, off);
            if (lane == 0) {
                float al = __expf(mold - mnew);
                al_s[row] = al;
                l_s[row] = l_s[row] * al + ps;
                m_s[row] = mnew;
            }
            Ps[row * 65 + lane * 2]     = p0;
            Ps[row * 65 + lane * 2 + 1] = p1;
        }
        __syncthreads();

        float al[4];
        #pragma unroll
        for (int i = 0; i < 4; i++) al[i] = al_s[ty * 4 + i];
        #pragma unroll
        for (int i = 0; i < 4; i++)
            #pragma unroll
            for (int j = 0; j < 4; j++) o[i][j] *= al[i];

        #pragma unroll 8
        for (int j = 0; j < 64; j++) {
            float pa[4], vb[4];
            #pragma unroll
            for (int i = 0; i < 4; i++) pa[i] = Ps[(ty * 4 + i) * 65 + j];
            #pragma unroll
            for (int c = 0; c < 4; c++) vb[c] = Vs[j * 65 + tx * 4 + c];
            #pragma unroll
            for (int i = 0; i < 4; i++)
                #pragma unroll
                for (int c = 0; c < 4; c++)
                    o[i][c] = fmaf(pa[i], vb[c], o[i][c]);
        }
        __syncthreads();
    }

    float linv[4];
    #pragma unroll
    for (int i = 0; i < 4; i++) linv[i] = 1.0f / l_s[ty * 4 + i];
    #pragma unroll
    for (int i = 0; i < 4; i++) {
        int row = b * NT + qb * 64 + ty * 4 + i;
        #pragma unroll
        for (int c = 0; c < 4; c++)
            g_attn[(size_t)row * ND + h * NHS + tx * 4 + c] = o[i][c] * linv[i];
    }
}

// ---------------- SwiGLU elementwise ----------------
__global__ void swiglu_kernel()
{
    int idx = blockIdx.x * blockDim.x + threadIdx.x;
    if (idx >= NBT * NHALF) return;
    int row = idx / NHALF;
    int c   = idx % NHALF;
    float a = g_u[(size_t)row * NFF + c];
    float z = g_u[(size_t)row * NFF + NHALF + c];
    float sg = z / (1.0f + __expf(-z));
    g_gl[idx] = sg * a;
}

// ---------------- launch ----------------
extern "C" void kernel_launch(void* const* d_in, const int* in_sizes, int n_in,
                              void* d_out, int out_size)
{
    const float* x  = (const float*)d_in[0];
    const float* Wq = (const float*)d_in[1];
    const float* Wk = (const float*)d_in[2];
    const float* Wv = (const float*)d_in[3];
    const float* Wo = (const float*)d_in[4];
    const float* bo = (const float*)d_in[5];
    const float* W1 = (const float*)d_in[6];
    const float* b1 = (const float*)d_in[7];
    const float* W2 = (const float*)d_in[8];
    const float* b2 = (const float*)d_in[9];
    const float* g1 = (const float*)d_in[10];
    const float* g2 = (const float*)d_in[11];
    float* out = (float*)d_out;

    const int ASMEM = (4 * 64 * 65 + 3 * 64) * (int)sizeof(float);  // 67328 B
    cudaFuncSetAttribute(attn_kernel, cudaFuncAttributeMaxDynamicSharedMemorySize, ASMEM);

    pack_wqkv_kernel<<<(ND * 3 * ND + 255) / 256, 256>>>(Wq, Wk, Wv);
    rmsnorm1_kernel<<<NBT, 256>>>(x, g1);
    gemm_qkv_kernel<<<dim3(3 * ND / 128, NBT / 128), 256>>>();
    attn_kernel<<<dim3(NT / 64, NH, NB), 256, ASMEM>>>();
    gemm_o_kernel<<<dim3(ND / 128, NBT / 128), 256>>>(Wo, bo, x);
    rmsnorm2_kernel<<<NBT, 256>>>(g2);
    gemm_ffn1_kernel<<<dim3(NFF / 128, NBT / 128), 256>>>(W1, b1);
    swiglu_kernel<<<(NBT * NHALF + 255) / 256, 256>>>();
    gemm_ffn2_kernel<<<dim3(ND / 128, NBT / 128), 256>>>(W2, b2, out);
}

// round 3
// speedup vs baseline: 3.0873x; 1.7499x over previous
#include <cuda_runtime.h>
#include <math.h>
#include <stdint.h>

// Problem constants
#define NB    2
#define NT    2048
#define ND    768
#define NH    12
#define NHS   64
#define NFF   3072
#define NHALF 1536
#define NBT   (NB*NT)   // 4096

// ---------------- scratch (device globals; no allocation) ----------------
__device__ float g_h   [NBT * ND];
__device__ float g_qkv [NBT * 3 * ND];
__device__ float g_attn[NBT * ND];
__device__ float g_x1  [NBT * ND];
__device__ float g_u   [NBT * NFF];
__device__ float g_gl  [NBT * NHALF];
__device__ float g_wqkv[ND * 3 * ND];

// ---------------- pack Wq/Wk/Wv (H,D,HS) -> B[768][2304] ----------------
__global__ void pack_wqkv_kernel(const float* __restrict__ Wq,
                                 const float* __restrict__ Wk,
                                 const float* __restrict__ Wv)
{
    int idx = blockIdx.x * blockDim.x + threadIdx.x;
    const int total = ND * 3 * ND;
    if (idx >= total) return;
    int d = idx / (3 * ND);
    int n = idx % (3 * ND);
    int m = n / ND;
    int r = n % ND;
    int h = r / NHS;
    int k = r % NHS;
    const float* W = (m == 0) ? Wq : ((m == 1) ? Wk : Wv);
    g_wqkv[idx] = W[h * ND * NHS + d * NHS + k];
}

// ---------------- RMSNorm ----------------
__device__ __forceinline__ void rms_body(const float* __restrict__ in,
                                         float* __restrict__ out,
                                         const float* __restrict__ g)
{
    int tid = threadIdx.x;
    float v0 = in[tid], v1 = in[tid + 256], v2 = in[tid + 512];
    float ss = v0*v0 + v1*v1 + v2*v2;
    #pragma unroll
    for (int o = 16; o; o >>= 1) ss += __shfl_xor_sync(0xffffffffu, ss, o);
    __shared__ float ws[8];
    __shared__ float s_inv;
    if ((tid & 31) == 0) ws[tid >> 5] = ss;
    __syncthreads();
    if (tid == 0) {
        float t = 0.f;
        #pragma unroll
        for (int i = 0; i < 8; i++) t += ws[i];
        float rms = sqrtf(t * (1.0f / (float)ND));
        s_inv = 1.0f / (rms + 1e-8f);
    }
    __syncthreads();
    float inv = s_inv;
    out[tid]       = g[tid]       * v0 * inv;
    out[tid + 256] = g[tid + 256] * v1 * inv;
    out[tid + 512] = g[tid + 512] * v2 * inv;
}

__global__ __launch_bounds__(256) void rmsnorm1_kernel(const float* __restrict__ x,
                                                       const float* __restrict__ g)
{
    int row = blockIdx.x;
    rms_body(x + (size_t)row * ND, g_h + (size_t)row * ND, g);
}

__global__ __launch_bounds__(256) void rmsnorm2_kernel(const float* __restrict__ g)
{
    int row = blockIdx.x;
    rms_body(g_x1 + (size_t)row * ND, g_h + (size_t)row * ND, g);
}

// ---------------- TF32 helpers ----------------
__device__ __forceinline__ float tf32r(float x)
{
    uint32_t r;
    asm("cvt.rna.tf32.f32 %0, %1;" : "=r"(r) : "f"(x));
    return __uint_as_float(r);
}

__device__ __forceinline__ void mma_tf32(float* c, const uint32_t* a, const uint32_t* b)
{
    asm volatile(
        "mma.sync.aligned.m16n8k8.row.col.f32.tf32.tf32.f32 "
        "{%0,%1,%2,%3}, {%4,%5,%6,%7}, {%8,%9}, {%0,%1,%2,%3};\n"
        : "+f"(c[0]), "+f"(c[1]), "+f"(c[2]), "+f"(c[3])
        : "r"(a[0]), "r"(a[1]), "r"(a[2]), "r"(a[3]), "r"(b[0]), "r"(b[1]));
}

// ---------------- TF32 tensor-core GEMM (128x128 tile) ----------------
template<int N, int K, bool BIAS, bool RES>
__device__ __forceinline__ void mma_gemm_body(const float* __restrict__ A,
                                              const float* __restrict__ Bm,
                                              float* __restrict__ C,
                                              const float* __restrict__ bias,
                                              const float* __restrict__ res)
{
    __shared__ float As[128][36];
    __shared__ float Bs[32][136];

    const int tid  = threadIdx.x;
    const int warp = tid >> 5, lane = tid & 31;
    const int wm = (warp >> 1) * 32;
    const int wn = (warp & 1) * 64;
    const int bm = blockIdx.y * 128;
    const int bn = blockIdx.x * 128;

    const int lrow = tid >> 3;
    const int lcol = (tid & 7) * 4;

    float acc[2][8][4];
    #pragma unroll
    for (int i = 0; i < 2; i++)
        #pragma unroll
        for (int j = 0; j < 8; j++)
            #pragma unroll
            for (int t = 0; t < 4; t++) acc[i][j][t] = 0.f;

    #pragma unroll 1
    for (int k0 = 0; k0 < K; k0 += 32) {
        #pragma unroll
        for (int r = 0; r < 4; r++) {
            int row = lrow + 32 * r;
            float4 v = *(const float4*)(A + (size_t)(bm + row) * K + k0 + lcol);
            As[row][lcol + 0] = tf32r(v.x);
            As[row][lcol + 1] = tf32r(v.y);
            As[row][lcol + 2] = tf32r(v.z);
            As[row][lcol + 3] = tf32r(v.w);
        }
        #pragma unroll
        for (int c = 0; c < 4; c++) {
            int col = lcol + 32 * c;
            float4 v = *(const float4*)(Bm + (size_t)(k0 + lrow) * N + bn + col);
            Bs[lrow][col + 0] = tf32r(v.x);
            Bs[lrow][col + 1] = tf32r(v.y);
            Bs[lrow][col + 2] = tf32r(v.z);
            Bs[lrow][col + 3] = tf32r(v.w);
        }
        __syncthreads();

        #pragma unroll
        for (int kk = 0; kk < 32; kk += 8) {
            uint32_t aF[2][4], bF[8][2];
            #pragma unroll
            for (int mt = 0; mt < 2; mt++) {
                int r = wm + mt * 16 + (lane >> 2);
                int c = kk + (lane & 3);
                aF[mt][0] = __float_as_uint(As[r][c]);
                aF[mt][1] = __float_as_uint(As[r + 8][c]);
                aF[mt][2] = __float_as_uint(As[r][c + 4]);
                aF[mt][3] = __float_as_uint(As[r + 8][c + 4]);
            }
            #pragma unroll
            for (int nt = 0; nt < 8; nt++) {
                int rr = kk + (lane & 3);
                int cc = wn + nt * 8 + (lane >> 2);
                bF[nt][0] = __float_as_uint(Bs[rr][cc]);
                bF[nt][1] = __float_as_uint(Bs[rr + 4][cc]);
            }
            #pragma unroll
            for (int mt = 0; mt < 2; mt++)
                #pragma unroll
                for (int nt = 0; nt < 8; nt++)
                    mma_tf32(acc[mt][nt], aF[mt], bF[nt]);
        }
        __syncthreads();
    }

    #pragma unroll
    for (int mt = 0; mt < 2; mt++) {
        #pragma unroll
        for (int nt = 0; nt < 8; nt++) {
            int row0 = bm + wm + mt * 16 + (lane >> 2);
            int col  = bn + wn + nt * 8 + (lane & 3) * 2;
            float2 v0 = make_float2(acc[mt][nt][0], acc[mt][nt][1]);
            float2 v1 = make_float2(acc[mt][nt][2], acc[mt][nt][3]);
            if constexpr (BIAS) {
                float2 bb = *(const float2*)(bias + col);
                v0.x += bb.x; v0.y += bb.y;
                v1.x += bb.x; v1.y += bb.y;
            }
            if constexpr (RES) {
                float2 r0 = *(const float2*)(res + (size_t)row0 * N + col);
                float2 r1 = *(const float2*)(res + (size_t)(row0 + 8) * N + col);
                v0.x += r0.x; v0.y += r0.y;
                v1.x += r1.x; v1.y += r1.y;
            }
            *(float2*)(C + (size_t)row0 * N + col)       = v0;
            *(float2*)(C + (size_t)(row0 + 8) * N + col) = v1;
        }
    }
}

__global__ __launch_bounds__(256) void gemm_qkv_kernel()
{
    mma_gemm_body<3 * ND, ND, false, false>(g_h, g_wqkv, g_qkv, nullptr, nullptr);
}
__global__ __launch_bounds__(256) void gemm_o_kernel(const float* __restrict__ Wo,
                                                     const float* __restrict__ bo,
                                                     const float* __restrict__ x)
{
    mma_gemm_body<ND, ND, true, true>(g_attn, Wo, g_x1, bo, x);
}
__global__ __launch_bounds__(256) void gemm_ffn1_kernel(const float* __restrict__ W1,
                                                        const float* __restrict__ b1)
{
    mma_gemm_body<NFF, ND, true, false>(g_h, W1, g_u, b1, nullptr);
}
__global__ __launch_bounds__(256) void gemm_ffn2_kernel(const float* __restrict__ W2,
                                                        const float* __restrict__ b2,
                                                        float* __restrict__ out)
{
    mma_gemm_body<ND, NHALF, true, true>(g_gl, W2, out, b2, g_x1);
}

// ---------------- Flash attention with tf32 MMA ----------------
// Block: 128 q-rows, 8 warps; warp w owns rows [w*16, w*16+16).
// S (16x64 per warp) lives in MMA C-fragments; softmax via quad shuffles.
// Smem strides: Q/K/P 68 (=4 mod 32, conflict-free row-spread LDS),
//               V 72 (=8 mod 32, conflict-free k-spread LDS).
#define QS_STR 68
#define KS_STR 68
#define VS_STR 72
#define PS_STR 68

__global__ __launch_bounds__(256) void attn_mma_kernel()
{
    extern __shared__ float sm[];
    float* Qs = sm;                      // [128][68]
    float* Ks = Qs + 128 * QS_STR;       // [64][68]
    float* Vs = Ks + 64 * KS_STR;        // [64][72]
    float* Ps = Vs + 64 * VS_STR;        // [128][68]

    const int tid  = threadIdx.x;
    const int warp = tid >> 5, lane = tid & 31;
    const int qb = (int)gridDim.x - 1 - (int)blockIdx.x;   // heavy blocks first
    const int h  = blockIdx.y;
    const int b  = blockIdx.z;
    const int row0 = qb * 128;          // first q row of block (within T)
    const int wrow = warp * 16;         // warp's row offset in tile

    const int lr = tid >> 4;            // 0..15
    const int lc = (tid & 15) * 4;      // 0..60

    // Load Q tile: 128 rows x 64 cols (tf32-rounded)
    #pragma unroll
    for (int r = 0; r < 8; r++) {
        int row = lr + 16 * r;
        float4 v = *(const float4*)&g_qkv[(size_t)(b * NT + row0 + row) * (3 * ND)
                                          + h * NHS + lc];
        float4 t = make_float4(tf32r(v.x), tf32r(v.y), tf32r(v.z), tf32r(v.w));
        *(float4*)&Qs[row * QS_STR + lc] = t;
    }

    float oacc[8][4];
    #pragma unroll
    for (int nt = 0; nt < 8; nt++)
        #pragma unroll
        for (int t = 0; t < 4; t++) oacc[nt][t] = 0.f;

    float m0 = -1e30f, m1 = -1e30f, l0 = 0.f, l1 = 0.f;
    const float scale = 0.03608439182435161f;   // 768^-0.5

    const int grow0 = row0 + wrow + (lane >> 2);   // global q pos of frag row
    const int grow1 = grow0 + 8;
    const int jb_max = 2 * qb + 1;

    for (int jb = 0; jb <= jb_max; jb++) {
        __syncthreads();   // previous iteration's K/V reads complete
        // Load K,V tiles: 64 rows x 64 cols
        #pragma unroll
        for (int r = 0; r < 4; r++) {
            int row = lr + 16 * r;
            size_t base = (size_t)(b * NT + jb * 64 + row) * (3 * ND) + h * NHS + lc;
            float4 kv = *(const float4*)&g_qkv[ND + base];
            float4 vv = *(const float4*)&g_qkv[2 * ND + base];
            float4 kt = make_float4(tf32r(kv.x), tf32r(kv.y), tf32r(kv.z), tf32r(kv.w));
            float4 vt = make_float4(tf32r(vv.x), tf32r(vv.y), tf32r(vv.z), tf32r(vv.w));
            *(float4*)&Ks[row * KS_STR + lc] = kt;
            *(float4*)&Vs[row * VS_STR + lc] = vt;
        }
        __syncthreads();

        // S = Q K^T (16x64 per warp, in C fragments)
        float sacc[8][4];
        #pragma unroll
        for (int nt = 0; nt < 8; nt++)
            #pragma unroll
            for (int t = 0; t < 4; t++) sacc[nt][t] = 0.f;

        #pragma unroll
        for (int kk = 0; kk < 64; kk += 8) {
            uint32_t aF[4];
            {
                int r = wrow + (lane >> 2);
                int c = kk + (lane & 3);
                aF[0] = __float_as_uint(Qs[r * QS_STR + c]);
                aF[1] = __float_as_uint(Qs[(r + 8) * QS_STR + c]);
                aF[2] = __float_as_uint(Qs[r * QS_STR + c + 4]);
                aF[3] = __float_as_uint(Qs[(r + 8) * QS_STR + c + 4]);
            }
            #pragma unroll
            for (int nt = 0; nt < 8; nt++) {
                uint32_t bF[2];
                int n = nt * 8 + (lane >> 2);
                int c = kk + (lane & 3);
                bF[0] = __float_as_uint(Ks[n * KS_STR + c]);
                bF[1] = __float_as_uint(Ks[n * KS_STR + c + 4]);
                mma_tf32(sacc[nt], aF, bF);
            }
        }

        // Scale + causal mask
        #pragma unroll
        for (int nt = 0; nt < 8; nt++) {
            int gcol = jb * 64 + nt * 8 + (lane & 3) * 2;
            float v0 = sacc[nt][0] * scale;
            float v1 = sacc[nt][1] * scale;
            float v2 = sacc[nt][2] * scale;
            float v3 = sacc[nt][3] * scale;
            if (gcol     > grow0) v0 = -1e30f;
            if (gcol + 1 > grow0) v1 = -1e30f;
            if (gcol     > grow1) v2 = -1e30f;
            if (gcol + 1 > grow1) v3 = -1e30f;
            sacc[nt][0] = v0; sacc[nt][1] = v1;
            sacc[nt][2] = v2; sacc[nt][3] = v3;
        }

        // Row max (quad reduce)
        float mx0 = -1e30f, mx1 = -1e30f;
        #pragma unroll
        for (int nt = 0; nt < 8; nt++) {
            mx0 = fmaxf(mx0, fmaxf(sacc[nt][0], sacc[nt][1]));
            mx1 = fmaxf(mx1, fmaxf(sacc[nt][2], sacc[nt][3]));
        }
        mx0 = fmaxf(mx0, __shfl_xor_sync(0xffffffffu, mx0, 1));
        mx0 = fmaxf(mx0, __shfl_xor_sync(0xffffffffu, mx0, 2));
        mx1 = fmaxf(mx1, __shfl_xor_sync(0xffffffffu, mx1, 1));
        mx1 = fmaxf(mx1, __shfl_xor_sync(0xffffffffu, mx1, 2));

        float mn0 = fmaxf(m0, mx0);
        float mn1 = fmaxf(m1, mx1);

        // Exponentiate + row sum
        float s0 = 0.f, s1 = 0.f;
        #pragma unroll
        for (int nt = 0; nt < 8; nt++) {
            float p0 = __expf(sacc[nt][0] - mn0);
            float p1 = __expf(sacc[nt][1] - mn0);
            float p2 = __expf(sacc[nt][2] - mn1);
            float p3 = __expf(sacc[nt][3] - mn1);
            sacc[nt][0] = p0; sacc[nt][1] = p1;
            sacc[nt][2] = p2; sacc[nt][3] = p3;
            s0 += p0 + p1;
            s1 += p2 + p3;
        }
        s0 += __shfl_xor_sync(0xffffffffu, s0, 1);
        s0 += __shfl_xor_sync(0xffffffffu, s0, 2);
        s1 += __shfl_xor_sync(0xffffffffu, s1, 1);
        s1 += __shfl_xor_sync(0xffffffffu, s1, 2);

        float al0 = __expf(m0 - mn0);
        float al1 = __expf(m1 - mn1);
        l0 = l0 * al0 + s0;
        l1 = l1 * al1 + s1;
        m0 = mn0; m1 = mn1;

        // Rescale O
        #pragma unroll
        for (int nt = 0; nt < 8; nt++) {
            oacc[nt][0] *= al0; oacc[nt][1] *= al0;
            oacc[nt][2] *= al1; oacc[nt][3] *= al1;
        }

        // Write P to smem (only this warp's rows; warp-local round trip)
        {
            int r = wrow + (lane >> 2);
            #pragma unroll
            for (int nt = 0; nt < 8; nt++) {
                int c = nt * 8 + (lane & 3) * 2;
                *(float2*)&Ps[r * PS_STR + c]       = make_float2(sacc[nt][0], sacc[nt][1]);
                *(float2*)&Ps[(r + 8) * PS_STR + c] = make_float2(sacc[nt][2], sacc[nt][3]);
            }
        }
        __syncwarp();

        // O += P @ V
        #pragma unroll
        for (int kk = 0; kk < 64; kk += 8) {
            uint32_t aF[4];
            {
                int r = wrow + (lane >> 2);
                int c = kk + (lane & 3);
                aF[0] = __float_as_uint(Ps[r * PS_STR + c]);
                aF[1] = __float_as_uint(Ps[(r + 8) * PS_STR + c]);
                aF[2] = __float_as_uint(Ps[r * PS_STR + c + 4]);
                aF[3] = __float_as_uint(Ps[(r + 8) * PS_STR + c + 4]);
            }
            #pragma unroll
            for (int nt = 0; nt < 8; nt++) {
                uint32_t bF[2];
                int s = kk + (lane & 3);
                int n = nt * 8 + (lane >> 2);
                bF[0] = __float_as_uint(Vs[s * VS_STR + n]);
                bF[1] = __float_as_uint(Vs[(s + 4) * VS_STR + n]);
                mma_tf32(oacc[nt], aF, bF);
            }
        }
    }

    // Normalize and store
    float li0 = 1.0f / l0, li1 = 1.0f / l1;
    {
        int r_g0 = b * NT + grow0;
        int r_g1 = b * NT + grow1;
        #pragma unroll
        for (int nt = 0; nt < 8; nt++) {
            int c = h * NHS + nt * 8 + (lane & 3) * 2;
            *(float2*)&g_attn[(size_t)r_g0 * ND + c] =
                make_float2(oacc[nt][0] * li0, oacc[nt][1] * li0);
            *(float2*)&g_attn[(size_t)r_g1 * ND + c] =
                make_float2(oacc[nt][2] * li1, oacc[nt][3] * li1);
        }
    }
}

// ---------------- SwiGLU elementwise ----------------
__global__ void swiglu_kernel()
{
    int idx = blockIdx.x * blockDim.x + threadIdx.x;
    if (idx >= NBT * NHALF) return;
    int row = idx / NHALF;
    int c   = idx % NHALF;
    float a = g_u[(size_t)row * NFF + c];
    float z = g_u[(size_t)row * NFF + NHALF + c];
    float sg = z / (1.0f + __expf(-z));
    g_gl[idx] = sg * a;
}

// ---------------- launch ----------------
extern "C" void kernel_launch(void* const* d_in, const int* in_sizes, int n_in,
                              void* d_out, int out_size)
{
    const float* x  = (const float*)d_in[0];
    const float* Wq = (const float*)d_in[1];
    const float* Wk = (const float*)d_in[2];
    const float* Wv = (const float*)d_in[3];
    const float* Wo = (const float*)d_in[4];
    const float* bo = (const float*)d_in[5];
    const float* W1 = (const float*)d_in[6];
    const float* b1 = (const float*)d_in[7];
    const float* W2 = (const float*)d_in[8];
    const float* b2 = (const float*)d_in[9];
    const float* g1 = (const float*)d_in[10];
    const float* g2 = (const float*)d_in[11];
    float* out = (float*)d_out;

    const int ASMEM = (128 * QS_STR + 64 * KS_STR + 64 * VS_STR + 128 * PS_STR)
                      * (int)sizeof(float);   // 105472 B
    cudaFuncSetAttribute(attn_mma_kernel, cudaFuncAttributeMaxDynamicSharedMemorySize, ASMEM);

    pack_wqkv_kernel<<<(ND * 3 * ND + 255) / 256, 256>>>(Wq, Wk, Wv);
    rmsnorm1_kernel<<<NBT, 256>>>(x, g1);
    gemm_qkv_kernel<<<dim3(3 * ND / 128, NBT / 128), 256>>>();
    attn_mma_kernel<<<dim3(NT / 128, NH, NB), 256, ASMEM>>>();
    gemm_o_kernel<<<dim3(ND / 128, NBT / 128), 256>>>(Wo, bo, x);
    rmsnorm2_kernel<<<NBT, 256>>>(g2);
    gemm_ffn1_kernel<<<dim3(NFF / 128, NBT / 128), 256>>>(W1, b1);
    swiglu_kernel<<<(NBT * NHALF + 255) / 256, 256>>>();
    gemm_ffn2_kernel<<<dim3(ND / 128, NBT / 128), 256>>>(W2, b2, out);
}